// round 1
// baseline (speedup 1.0000x reference)
#include <cuda_runtime.h>

// Problem constants
#define NN 64
#define CC 256
#define TT 64
#define VV 25
#define VP 28                  // padded V (float4/u64-friendly row stride: 112B)
#define NT (NN * TT)           // 4096 CTAs per block-kernel
#define ELEMS (NN * CC * TT * VV)

// Ping-pong scratch for the inter-block residual tensors (no cudaMalloc allowed)
__device__ float g_buf0[ELEMS];
__device__ float g_buf1[ELEMS];

// Packed fp32x2 FMA (sm_100+ only; ptxas never auto-fuses this — inline PTX required)
__device__ __forceinline__ unsigned long long ffma2(unsigned long long a,
                                                    unsigned long long b,
                                                    unsigned long long c) {
    unsigned long long d;
    asm("fma.rn.f32x2 %0, %1, %2, %3;" : "=l"(d) : "l"(a), "l"(b), "l"(c));
    return d;
}

__device__ __forceinline__ unsigned long long pack2(float x) {
    unsigned long long d;
    unsigned xu = __float_as_uint(x);
    asm("mov.b64 %0, {%1, %2};" : "=l"(d) : "r"(xu), "r"(xu));
    return d;
}

// Shared memory layout (floats):
//   sx:  CC*VP  (x slab, also the residual)
//   sy:  CC*VP  (y = x @ A^T, later reused as output staging)
//   sA:  640    (25x25 A matrix, padded)
//   wt:  32*257 (transposed W tile, 257-stride => conflict-free)
#define SX_OFF  0
#define SY_OFF  (CC * VP)
#define SA_OFF  (2 * CC * VP)
#define WT_OFF  (2 * CC * VP + 640)
#define SMEM_FLOATS (2 * CC * VP + 640 + 32 * 257)
#define SMEM_BYTES  (SMEM_FLOATS * 4)

__global__ void __launch_bounds__(256, 2)
ode_block_kernel(const float* __restrict__ in,   // residual input [N,C,T,V]
                 const float* __restrict__ Amat, // [V,V]
                 const float* __restrict__ w,    // [C,C] (row o, col c)
                 const float* __restrict__ b,    // [C]
                 float* __restrict__ out)        // [N,C,T,V]
{
    extern __shared__ float smem[];
    float* sx = smem + SX_OFF;
    float* sy = smem + SY_OFF;
    float* sA = smem + SA_OFF;
    float* wt = smem + WT_OFF;

    const int tid = threadIdx.x;
    const int nt  = blockIdx.x;
    const int n   = nt / TT;
    const int t   = nt - n * TT;
    // index(n,c,t,v) = ((n*C + c)*T + t)*V + v
    const long base = (long)n * (CC * TT * VV) + (long)t * VV;

    // ---- Load A (25x25) and the x slab [C][V] ----
    for (int i = tid; i < VV * VV; i += 256) sA[i] = Amat[i];
    for (int i = tid; i < CC * VV; i += 256) {
        int c = i / VV;
        int v = i - c * VV;
        sx[c * VP + v] = in[base + (long)c * (TT * VV) + v];
    }
    __syncthreads();

    // ---- Phase 1: y[c][v] = sum_u A[v][u] * x[c][u]  (thread c = tid) ----
    {
        float xr[VV];
#pragma unroll
        for (int u = 0; u < VV; u++) xr[u] = sx[tid * VP + u];
#pragma unroll
        for (int v = 0; v < VV; v++) {
            float s = 0.f;
#pragma unroll
            for (int u = 0; u < VV; u++) s = fmaf(sA[v * VV + u], xr[u], s);
            sy[tid * VP + v] = s;
        }
        // zero the padding lanes so packed-f32x2 reads are well-defined
        sy[tid * VP + 25] = 0.f;
        sy[tid * VP + 26] = 0.f;
        sy[tid * VP + 27] = 0.f;
    }
    __syncthreads();

    // ---- Phase 2: out[o][v] = sum_c w[o][c] * y[c][v], thread owns o = tid ----
    unsigned long long acc[13];
#pragma unroll
    for (int j = 0; j < 13; j++) acc[j] = 0ULL;

    for (int cc = 0; cc < CC; cc += 32) {
        // Stage transposed W tile: wt[cl][o] = w[o][cc+cl]
        // global read coalesced (consecutive cl), smem write conflict-free (stride 257)
        for (int i = tid; i < 32 * CC; i += 256) {
            int o  = i >> 5;
            int cl = i & 31;
            wt[cl * 257 + o] = w[o * CC + cc + cl];
        }
        __syncthreads();

#pragma unroll 4
        for (int cl = 0; cl < 32; cl++) {
            unsigned long long wv2 = pack2(wt[cl * 257 + tid]);   // conflict-free LDS
            const unsigned long long* yrow =
                reinterpret_cast<const unsigned long long*>(sy + (cc + cl) * VP); // broadcast
#pragma unroll
            for (int j = 0; j < 13; j++) acc[j] = ffma2(yrow[j], wv2, acc[j]);
        }
        __syncthreads();
    }

    // ---- Phase 3: epilogue relu(acc + b[o] + x[o][v]) ----
    float bias = b[tid];
    float rr[VV + 1];
#pragma unroll
    for (int j = 0; j < 13; j++) {
        unsigned long long a = acc[j];
        rr[2 * j]     = __uint_as_float((unsigned)(a & 0xffffffffULL));
        rr[2 * j + 1] = __uint_as_float((unsigned)(a >> 32));
    }
#pragma unroll
    for (int v = 0; v < VV; v++) {
        float val = rr[v] + bias + sx[tid * VP + v];
        rr[v] = val > 0.f ? val : 0.f;
    }

    __syncthreads();   // everyone is done reading sy — safe to reuse as staging
#pragma unroll
    for (int v = 0; v < VV; v++) sy[tid * VP + v] = rr[v];
    __syncthreads();

    for (int i = tid; i < CC * VV; i += 256) {
        int c = i / VV;
        int v = i - c * VV;
        out[base + (long)c * (TT * VV) + v] = sy[c * VP + v];
    }
}

extern "C" void kernel_launch(void* const* d_in, const int* in_sizes, int n_in,
                              void* d_out, int out_size)
{
    // metadata order: t, x, A, w1, b1, w2, b2, w3, b3, w4, b4
    const float* x  = (const float*)d_in[1];
    const float* A  = (const float*)d_in[2];
    const float* w1 = (const float*)d_in[3];
    const float* b1 = (const float*)d_in[4];
    const float* w2 = (const float*)d_in[5];
    const float* b2 = (const float*)d_in[6];
    const float* w3 = (const float*)d_in[7];
    const float* b3 = (const float*)d_in[8];
    const float* w4 = (const float*)d_in[9];
    const float* b4 = (const float*)d_in[10];
    float* out = (float*)d_out;

    float *buf0, *buf1;
    cudaGetSymbolAddress((void**)&buf0, g_buf0);
    cudaGetSymbolAddress((void**)&buf1, g_buf1);

    cudaFuncSetAttribute(ode_block_kernel,
                         cudaFuncAttributeMaxDynamicSharedMemorySize, SMEM_BYTES);

    ode_block_kernel<<<NT, 256, SMEM_BYTES>>>(x,    A, w1, b1, buf0);
    ode_block_kernel<<<NT, 256, SMEM_BYTES>>>(buf0, A, w2, b2, buf1);
    ode_block_kernel<<<NT, 256, SMEM_BYTES>>>(buf1, A, w3, b3, buf0);
    ode_block_kernel<<<NT, 256, SMEM_BYTES>>>(buf0, A, w4, b4, out);
}